// round 3
// baseline (speedup 1.0000x reference)
#include <cuda_runtime.h>

#define NB   2
#define NN   512
#define IND  512
#define MEMD 300
#define HIDD 64
#define NEG_SLOPE 0.01f
#define GRIDSZ 148
#define NTHR 256

#define BM 32
#define BN 64
#define BK 16
#define TI 32
#define TJ 128

// ---------------- scratch (allocation-free: __device__ globals) -------------
__device__ float g_h[NB * NN * MEMD];
__device__ float g_out1[NB * NN * MEMD];
__device__ float g_siT[NB * HIDD * NN];
__device__ float g_sjT[NB * HIDD * NN];
__device__ float g_p[NB * NN * NN];
__device__ float g_partial[NB * 64];
__device__ unsigned g_bar_count;   // zero-init
__device__ unsigned g_bar_gen;     // monotonically increasing across replays

// ---------------- grid-wide barrier (replay-safe, sense = base+k) -----------
__device__ __forceinline__ void grid_bar(unsigned target)
{
    __threadfence();          // make this thread's writes globally visible
    __syncthreads();          // all block threads' fences done
    if (threadIdx.x == 0) {
        if (atomicAdd(&g_bar_count, 1u) == GRIDSZ - 1u) {
            g_bar_count = 0u;
            __threadfence();
            *(volatile unsigned*)&g_bar_gen = target;
        } else {
            while ((int)(*(volatile unsigned*)&g_bar_gen - target) < 0) { }
        }
        __threadfence();      // acquire + L1D invalidate (CCTL.IVALL)
    }
    __syncthreads();
}

// ---------------- smem layout (union across phases) -------------------------
// pair:  Si 8448B | Sj 33024B | W 256B | red 1024B   (= 42752)
// gemm:  As 2112B | Bs 4160B                          (= 6272)
// s:     hrow 2400B
// invZ:  at offset 43520 (8B)
#define SM_BYTES 44544
#define SM_SJ_OFF   (sizeof(float) * HIDD * (TI + 1))
#define SM_W_OFF    (SM_SJ_OFF + sizeof(float) * HIDD * (TJ + 1))
#define SM_RED_OFF  (SM_W_OFF + sizeof(float) * HIDD)
#define SM_INVZ_OFF 43520
#define SM_BS_OFF   (sizeof(float) * BK * (BM + 1))

// ---------------- generic tiled GEMM phase: C = scale*(A@B) + bias ----------
// block-stride over (batches x rowTiles x colTiles). M must be multiple of BM.
__device__ void gemm_phase(unsigned char* SM,
                           const float* __restrict__ A, long long sA,
                           const float* __restrict__ Bmat, long long sB,
                           float* __restrict__ C, long long sC,
                           int M, int N, int K,
                           const float* __restrict__ bias,
                           const float* scaleArr, int batches)
{
    float (*As)[BM + 1] = (float(*)[BM + 1])SM;
    float (*Bs)[BN + 1] = (float(*)[BN + 1])(SM + SM_BS_OFF);

    int tid = threadIdx.x;
    int tx = tid & 15, ty = tid >> 4;
    int colT = (N + BN - 1) / BN;
    int rowT = M / BM;
    int T = colT * rowT * batches;

    for (int t = blockIdx.x; t < T; t += GRIDSZ) {
        int bz = t / (colT * rowT);
        int r = t - bz * colT * rowT;
        int byy = r / colT, bxx = r - byy * colT;
        const float* Ab = A + bz * sA;
        const float* Bb = Bmat + bz * sB;
        float* Cb = C + bz * sC;
        int row0 = byy * BM, col0 = bxx * BN;

        float acc[2][4] = {};
        for (int k0 = 0; k0 < K; k0 += BK) {
            __syncthreads();
            #pragma unroll
            for (int l = 0; l < (BM * BK) / NTHR; l++) {
                int idx = tid + l * NTHR;
                int m = idx / BK, kk = idx - m * BK;
                int k = k0 + kk;
                As[kk][m] = (k < K) ? Ab[(long long)(row0 + m) * K + k] : 0.f;
            }
            #pragma unroll
            for (int l = 0; l < (BK * BN) / NTHR; l++) {
                int idx = tid + l * NTHR;
                int kk = idx / BN, n = idx - kk * BN;
                int k = k0 + kk, c = col0 + n;
                Bs[kk][n] = (k < K && c < N) ? Bb[(long long)k * N + c] : 0.f;
            }
            __syncthreads();
            #pragma unroll
            for (int kk = 0; kk < BK; kk++) {
                float a0 = As[kk][ty], a1 = As[kk][ty + 16];
                float b0 = Bs[kk][tx],      b1 = Bs[kk][tx + 16];
                float b2 = Bs[kk][tx + 32], b3 = Bs[kk][tx + 48];
                acc[0][0] += a0 * b0; acc[0][1] += a0 * b1;
                acc[0][2] += a0 * b2; acc[0][3] += a0 * b3;
                acc[1][0] += a1 * b0; acc[1][1] += a1 * b1;
                acc[1][2] += a1 * b2; acc[1][3] += a1 * b3;
            }
        }
        __syncthreads();

        float sc = scaleArr ? scaleArr[bz] : 1.f;
        #pragma unroll
        for (int i = 0; i < 2; i++) {
            int rr = row0 + ty + 16 * i;
            #pragma unroll
            for (int j = 0; j < 4; j++) {
                int c = col0 + tx + 16 * j;
                if (c < N) {
                    float v = acc[i][j] * sc;
                    if (bias) v += bias[c];
                    Cb[(long long)rr * N + c] = v;
                }
            }
        }
    }
}

// ---------------- s projections: siT/sjT (transposed, bias folded) ----------
__device__ void s_phase(unsigned char* SM, const float* __restrict__ h,
                        const float* __restrict__ a1w,
                        const float* __restrict__ a1b)
{
    float (*hrow)[MEMD] = (float(*)[MEMD])SM;
    int tid = threadIdx.x;
    int half = tid >> 7;      // which of the 2 rows this thread handles
    int lt = tid & 127;
    int hcol = lt & 63;
    bool is_j = lt >= 64;
    const float* w = a1w + (is_j ? MEMD * HIDD : 0);

    for (int r0 = blockIdx.x * 2; r0 < NB * NN; r0 += GRIDSZ * 2) {
        __syncthreads();
        for (int k = tid; k < 2 * MEMD; k += NTHR) {
            int rr = k / MEMD, kk = k - rr * MEMD;
            hrow[rr][kk] = h[(r0 + rr) * MEMD + kk];
        }
        __syncthreads();

        float acc0 = 0.f, acc1 = 0.f;
        #pragma unroll 4
        for (int k = 0; k < MEMD; k += 2) {       // MEMD even
            acc0 += hrow[half][k]     * w[k * HIDD + hcol];
            acc1 += hrow[half][k + 1] * w[(k + 1) * HIDD + hcol];
        }
        float acc = acc0 + acc1;

        int row = r0 + half;
        int b = row >> 9, i = row & 511;
        if (is_j) g_sjT[(b * HIDD + hcol) * NN + i] = acc + a1b[hcol];
        else      g_siT[(b * HIDD + hcol) * NN + i] = acc;
    }
}

// ---------------- pairwise: p = adj*exp(leaky(e)), partial Z ----------------
__device__ void pair_phase(unsigned char* SM,
                           const float* __restrict__ adj,
                           const float* __restrict__ a2w,
                           const float* __restrict__ a2b)
{
    float (*Si)[TI + 1] = (float(*)[TI + 1])SM;
    float (*Sj)[TJ + 1] = (float(*)[TJ + 1])(SM + SM_SJ_OFF);
    float* W   = (float*)(SM + SM_W_OFF);
    float* red = (float*)(SM + SM_RED_OFF);

    int tid = threadIdx.x;
    int tx = tid & 31, ty = tid >> 5;
    const int Tt = NB * (NN / TI) * (NN / TJ);    // 128

    for (int t = blockIdx.x; t < Tt; t += GRIDSZ) {
        int b = t >> 6;
        int rem = t & 63;
        int by = rem >> 2, bx = rem & 3;
        int i0 = by * TI, j0 = bx * TJ;

        __syncthreads();
        for (int idx = tid; idx < HIDD * TI; idx += NTHR) {
            int h = idx / TI, r = idx - h * TI;
            Si[h][r] = g_siT[(b * HIDD + h) * NN + i0 + r];
        }
        for (int idx = tid; idx < HIDD * TJ; idx += NTHR) {
            int h = idx / TJ, r = idx - h * TJ;
            Sj[h][r] = g_sjT[(b * HIDD + h) * NN + j0 + r];
        }
        if (tid < HIDD) W[tid] = a2w[tid];
        __syncthreads();

        float acc[4][4] = {};
        #pragma unroll 8
        for (int h = 0; h < HIDD; h++) {
            float w = W[h];
            float a[4], bb[4];
            #pragma unroll
            for (int ii = 0; ii < 4; ii++) a[ii] = Si[h][ty + 8 * ii];
            #pragma unroll
            for (int jj = 0; jj < 4; jj++) bb[jj] = Sj[h][tx + 32 * jj];
            #pragma unroll
            for (int ii = 0; ii < 4; ii++)
                #pragma unroll
                for (int jj = 0; jj < 4; jj++) {
                    float x = a[ii] + bb[jj];
                    acc[ii][jj] += fmaxf(x, 0.f) * w;
                }
        }

        float a2bv = a2b[0];
        float psum = 0.f;
        #pragma unroll
        for (int ii = 0; ii < 4; ii++) {
            int i = i0 + ty + 8 * ii;
            #pragma unroll
            for (int jj = 0; jj < 4; jj++) {
                int j = j0 + tx + 32 * jj;
                float e = acc[ii][jj] + a2bv;
                e = e > 0.f ? e : NEG_SLOPE * e;
                float ad = adj[((long long)b * NN + i) * NN + j];
                float pv = ad * __expf(e);
                g_p[((long long)b * NN + i) * NN + j] = pv;
                psum += pv;
            }
        }

        red[tid] = psum;
        __syncthreads();
        for (int s = 128; s > 0; s >>= 1) {
            if (tid < s) red[tid] += red[tid + s];
            __syncthreads();
        }
        if (tid == 0) g_partial[b * 64 + rem] = red[0];
    }
}

// ---------------- invZ (redundant per block) + out = invZ * p@h -------------
__device__ void out_phase(unsigned char* SM, const float* hbuf, float* outbuf)
{
    float* invZ = (float*)(SM + SM_INVZ_OFF);
    int tid = threadIdx.x;
    if (tid < NB) {
        float s = 0.f;
        #pragma unroll
        for (int k = 0; k < 64; k++) s += g_partial[tid * 64 + k];
        invZ[tid] = 1.f / s;
    }
    __syncthreads();
    gemm_phase(SM, g_p, (long long)NN * NN, hbuf, (long long)NN * MEMD,
               outbuf, (long long)NN * MEMD,
               NN, MEMD, NN, nullptr, invZ, NB);
}

// ---------------- the one persistent kernel ---------------------------------
__global__ void __launch_bounds__(NTHR, 1) fused_gat(
    const float* __restrict__ feature, const float* __restrict__ adj,
    const float* __restrict__ w0, const float* __restrict__ b0,
    const float* __restrict__ w1, const float* __restrict__ b1,
    const float* __restrict__ a1w, const float* __restrict__ a1b,
    const float* __restrict__ a2w, const float* __restrict__ a2b,
    float* __restrict__ out)
{
    __shared__ __align__(16) unsigned char SM[SM_BYTES];
    __shared__ unsigned s_base;
    if (threadIdx.x == 0) s_base = *(volatile unsigned*)&g_bar_gen;
    __syncthreads();
    unsigned bb = s_base;

    // -------- layer 1 --------
    gemm_phase(SM, feature, 0, w0, 0, g_h, 0, NB * NN, MEMD, IND, b0, nullptr, 1);
    grid_bar(bb + 1);
    s_phase(SM, g_h, a1w, a1b);
    grid_bar(bb + 2);
    pair_phase(SM, adj, a2w, a2b);
    grid_bar(bb + 3);
    out_phase(SM, g_h, g_out1);
    grid_bar(bb + 4);

    // -------- layer 2 --------
    gemm_phase(SM, g_out1, 0, w1, 0, g_h, 0, NB * NN, MEMD, MEMD, b1, nullptr, 1);
    grid_bar(bb + 5);
    s_phase(SM, g_h, a1w, a1b);
    grid_bar(bb + 6);
    pair_phase(SM, adj, a2w, a2b);
    grid_bar(bb + 7);
    out_phase(SM, g_h, out);
}

// ---------------- host launcher ---------------------------------------------
extern "C" void kernel_launch(void* const* d_in, const int* in_sizes, int n_in,
                              void* d_out, int out_size)
{
    const float* feature = (const float*)d_in[0];
    const float* adj     = (const float*)d_in[1];
    const float* w0      = (const float*)d_in[2];
    const float* b0      = (const float*)d_in[3];
    const float* w1      = (const float*)d_in[4];
    const float* b1      = (const float*)d_in[5];
    const float* a1w     = (const float*)d_in[6];
    const float* a1b     = (const float*)d_in[7];
    const float* a2w     = (const float*)d_in[8];
    const float* a2b     = (const float*)d_in[9];
    float* out = (float*)d_out;

    fused_gat<<<GRIDSZ, NTHR>>>(feature, adj, w0, b0, w1, b1,
                                a1w, a1b, a2w, a2b, out);
}